// round 1
// baseline (speedup 1.0000x reference)
#include <cuda_runtime.h>

// ---------------------------------------------------------------------------
// SingleHeadAttention: B=4, T=4096, C=1024
//   qkv = x @ w_qkv^T               [16384 x 3072]
//   S   = causal(Q K^T * C^-0.5)    per batch [4096 x 4096]
//   P   = softmax_rows(S)
//   O   = P V                        [4096 x 1024] per batch
//   Y   = O @ w_out^T                [16384 x 1024]
// All fp32. Causality exploited at tile granularity in both attention GEMMs.
// ---------------------------------------------------------------------------

#define BM 128
#define BN 128
#define BK 16
#define TM 8
#define TN 8
// 256 threads = (BM/TM) * (BN/TN)

static const int Bc = 4;
static const int Tc = 4096;
static const int Cc = 1024;

// Static device scratch (allocation-free rule): 192 + 256 + 64 MB
__device__ float g_qkv[(size_t)16384 * 3072];
__device__ float g_s[(size_t)4 * 4096 * 4096];
__device__ float g_o[(size_t)16384 * 1024];

// C[m,n] = alpha * sum_k A[m,k] * B[n,k]   (both K-major: "NT")
// causal: skip tiles strictly above the block diagonal (n0 > m0+BM-1)
__global__ __launch_bounds__(256) void gemm_nt(
    const float* __restrict__ A, const float* __restrict__ B,
    float* __restrict__ C,
    int M, int N, int K, int lda, int ldb, int ldc,
    long strideA, long strideB, long strideC,
    float alpha, int causal)
{
    int bn = blockIdx.x, bm = blockIdx.y, bz = blockIdx.z;
    int m0 = bm * BM, n0 = bn * BN;
    if (causal && n0 > m0 + (BM - 1)) return;

    A += (long)bz * strideA;
    B += (long)bz * strideB;
    C += (long)bz * strideC;

    __shared__ float As[BK][BM];
    __shared__ float Bs[BK][BN];

    int tid = threadIdx.x;
    int tx = tid & 15;        // n direction
    int ty = tid >> 4;        // m direction

    float acc[TM][TN];
#pragma unroll
    for (int i = 0; i < TM; i++)
#pragma unroll
        for (int j = 0; j < TN; j++) acc[i][j] = 0.f;

    for (int k0 = 0; k0 < K; k0 += BK) {
        // Load A tile (BM x BK) and B tile (BN x BK), both K-major, transpose to smem.
#pragma unroll
        for (int i = 0; i < 2; i++) {
            int idx = tid + i * 256;          // 0..511
            int row = idx >> 2;               // 0..127
            int c4  = idx & 3;                // 0..3  (k chunk of 4)
            float4 a = *(const float4*)&A[(size_t)(m0 + row) * lda + k0 + c4 * 4];
            As[c4 * 4 + 0][row] = a.x;
            As[c4 * 4 + 1][row] = a.y;
            As[c4 * 4 + 2][row] = a.z;
            As[c4 * 4 + 3][row] = a.w;
            float4 b = *(const float4*)&B[(size_t)(n0 + row) * ldb + k0 + c4 * 4];
            Bs[c4 * 4 + 0][row] = b.x;
            Bs[c4 * 4 + 1][row] = b.y;
            Bs[c4 * 4 + 2][row] = b.z;
            Bs[c4 * 4 + 3][row] = b.w;
        }
        __syncthreads();

#pragma unroll
        for (int k = 0; k < BK; k++) {
            float ra[TM], rb[TN];
#pragma unroll
            for (int i = 0; i < TM; i++) ra[i] = As[k][ty * TM + i];
#pragma unroll
            for (int j = 0; j < TN; j++) rb[j] = Bs[k][tx * TN + j];
#pragma unroll
            for (int i = 0; i < TM; i++)
#pragma unroll
                for (int j = 0; j < TN; j++) acc[i][j] += ra[i] * rb[j];
        }
        __syncthreads();
    }

#pragma unroll
    for (int i = 0; i < TM; i++) {
        size_t crow = (size_t)(m0 + ty * TM + i) * ldc + n0 + tx * TN;
#pragma unroll
        for (int j = 0; j < TN; j += 4) {
            float4 v;
            v.x = alpha * acc[i][j + 0];
            v.y = alpha * acc[i][j + 1];
            v.z = alpha * acc[i][j + 2];
            v.w = alpha * acc[i][j + 3];
            *(float4*)&C[crow + j] = v;
        }
    }
}

// C[m,n] = sum_k A[m,k] * B[k,n]   (A K-major, B N-major: "NN")
// causal: K-loop bounded at m0+BM (P is zero beyond the row-tile diagonal)
__global__ __launch_bounds__(256) void gemm_nn(
    const float* __restrict__ A, const float* __restrict__ B,
    float* __restrict__ C,
    int M, int N, int K, int lda, int ldb, int ldc,
    long strideA, long strideB, long strideC,
    int causal)
{
    int bn = blockIdx.x, bm = blockIdx.y, bz = blockIdx.z;
    int m0 = bm * BM, n0 = bn * BN;

    A += (long)bz * strideA;
    B += (long)bz * strideB;
    C += (long)bz * strideC;

    int Kb = causal ? min(K, m0 + BM) : K;

    __shared__ float As[BK][BM];
    __shared__ float Bs[BK][BN];

    int tid = threadIdx.x;
    int tx = tid & 15;
    int ty = tid >> 4;

    float acc[TM][TN];
#pragma unroll
    for (int i = 0; i < TM; i++)
#pragma unroll
        for (int j = 0; j < TN; j++) acc[i][j] = 0.f;

    for (int k0 = 0; k0 < Kb; k0 += BK) {
#pragma unroll
        for (int i = 0; i < 2; i++) {
            int idx = tid + i * 256;
            {   // A: BM x BK, K-major -> transpose into As
                int row = idx >> 2;
                int c4  = idx & 3;
                float4 a = *(const float4*)&A[(size_t)(m0 + row) * lda + k0 + c4 * 4];
                As[c4 * 4 + 0][row] = a.x;
                As[c4 * 4 + 1][row] = a.y;
                As[c4 * 4 + 2][row] = a.z;
                As[c4 * 4 + 3][row] = a.w;
            }
            {   // B: BK x BN, N-major -> direct copy
                int krow = idx >> 5;          // 0..15
                int c4   = idx & 31;          // 0..31
                float4 b = *(const float4*)&B[(size_t)(k0 + krow) * ldb + n0 + c4 * 4];
                *(float4*)&Bs[krow][c4 * 4] = b;
            }
        }
        __syncthreads();

#pragma unroll
        for (int k = 0; k < BK; k++) {
            float ra[TM], rb[TN];
#pragma unroll
            for (int i = 0; i < TM; i++) ra[i] = As[k][ty * TM + i];
#pragma unroll
            for (int j = 0; j < TN; j++) rb[j] = Bs[k][tx * TN + j];
#pragma unroll
            for (int i = 0; i < TM; i++)
#pragma unroll
                for (int j = 0; j < TN; j++) acc[i][j] += ra[i] * rb[j];
        }
        __syncthreads();
    }

#pragma unroll
    for (int i = 0; i < TM; i++) {
        size_t crow = (size_t)(m0 + ty * TM + i) * ldc + n0 + tx * TN;
#pragma unroll
        for (int j = 0; j < TN; j += 4) {
            float4 v;
            v.x = acc[i][j + 0];
            v.y = acc[i][j + 1];
            v.z = acc[i][j + 2];
            v.w = acc[i][j + 3];
            *(float4*)&C[crow + j] = v;
        }
    }
}

// One block per attention row (b*T + t). Softmax over [0, t], then zero-pad
// (t, tile_end) so the PV GEMM can read whole 128-wide K tiles.
__global__ __launch_bounds__(256) void softmax_causal(float* __restrict__ S, int T)
{
    int row = blockIdx.x;            // b*T + t
    int t = row & (T - 1);           // T = 4096 (pow2)
    float* p = S + (size_t)row * T;
    int len = t + 1;
    int tid = threadIdx.x;

    __shared__ float red[256];

    // 1) max
    float m = -1e30f;
    for (int i = tid; i < len; i += 256) m = fmaxf(m, p[i]);
    red[tid] = m;
    __syncthreads();
    for (int s = 128; s > 0; s >>= 1) {
        if (tid < s) red[tid] = fmaxf(red[tid], red[tid + s]);
        __syncthreads();
    }
    m = red[0];
    __syncthreads();

    // 2) exp + sum
    float sum = 0.f;
    for (int i = tid; i < len; i += 256) {
        float e = __expf(p[i] - m);
        p[i] = e;
        sum += e;
    }
    red[tid] = sum;
    __syncthreads();
    for (int s = 128; s > 0; s >>= 1) {
        if (tid < s) red[tid] += red[tid + s];
        __syncthreads();
    }
    float inv = 1.0f / red[0];

    // 3) normalize
    for (int i = tid; i < len; i += 256) p[i] *= inv;

    // 4) zero pad (t, tile_end) so PV can use full 128-wide K tiles
    int pad_end = ((t >> 7) + 1) << 7;
    for (int i = len + tid; i < pad_end; i += 256) p[i] = 0.f;
}

extern "C" void kernel_launch(void* const* d_in, const int* in_sizes, int n_in,
                              void* d_out, int out_size)
{
    const float* x     = (const float*)d_in[0];
    // d_in[1] = mask (bool tril) -- causality is hardcoded
    const float* w_qkv = (const float*)d_in[2];
    const float* w_out = (const float*)d_in[3];
    float* y = (float*)d_out;

    float *qkv, *s, *o;
    cudaGetSymbolAddress((void**)&qkv, g_qkv);
    cudaGetSymbolAddress((void**)&s,   g_s);
    cudaGetSymbolAddress((void**)&o,   g_o);

    const int M  = Bc * Tc;        // 16384
    const float scale = 0.03125f;  // C^-0.5 = 1/32

    dim3 thr(256);

    // 1) qkv = x @ w_qkv^T : [16384 x 3072], K=1024
    gemm_nt<<<dim3(3072 / BN, M / BM, 1), thr>>>(
        x, w_qkv, qkv, M, 3072, Cc, Cc, Cc, 3072,
        0, 0, 0, 1.f, 0);

    // 2) S = scale * Q K^T per batch (causal tile skip)
    //    Q = qkv + 0, K = qkv + 1024, row stride 3072
    gemm_nt<<<dim3(Tc / BN, Tc / BM, Bc), thr>>>(
        qkv, qkv + 1024, s, Tc, Tc, Cc, 3072, 3072, Tc,
        (long)Tc * 3072, (long)Tc * 3072, (long)Tc * Tc,
        scale, 1);

    // 3) row softmax + causal zero-pad
    softmax_causal<<<Bc * Tc, thr>>>(s, Tc);

    // 4) O = P V per batch (K bounded at row-tile diagonal)
    //    V = qkv + 2048, N-major with ldb=3072
    gemm_nn<<<dim3(Cc / BN, Tc / BM, Bc), thr>>>(
        s, qkv + 2048, o, Tc, Cc, Tc, Tc, 3072, Cc,
        (long)Tc * Tc, (long)Tc * 3072, (long)Tc * Cc,
        1);

    // 5) Y = O @ w_out^T : [16384 x 1024], K=1024
    gemm_nt<<<dim3(Cc / BN, M / BM, 1), thr>>>(
        o, w_out, y, M, Cc, Cc, Cc, Cc, Cc,
        0, 0, 0, 1.f, 0);
}

// round 2
// speedup vs baseline: 1.0001x; 1.0001x over previous
#include <cuda_runtime.h>

// ---------------------------------------------------------------------------
// SingleHeadAttention: B=4, T=4096, C=1024
//   qkv = x @ w_qkv^T               [16384 x 3072]
//   S   = causal(Q K^T * C^-0.5)    per batch [4096 x 4096]
//   P   = softmax_rows(S)
//   O   = P V                        [4096 x 1024] per batch
//   Y   = O @ w_out^T                [16384 x 1024]
// All fp32. Causality exploited at tile granularity in both attention GEMMs.
// ---------------------------------------------------------------------------

#define BM 128
#define BN 128
#define BK 16
#define TM 8
#define TN 8
// 256 threads = (BM/TM) * (BN/TN)

static const int Bc = 4;
static const int Tc = 4096;
static const int Cc = 1024;

// Static device scratch (allocation-free rule): 192 + 256 + 64 MB
__device__ float g_qkv[(size_t)16384 * 3072];
__device__ float g_s[(size_t)4 * 4096 * 4096];
__device__ float g_o[(size_t)16384 * 1024];

// C[m,n] = alpha * sum_k A[m,k] * B[n,k]   (both K-major: "NT")
// causal: skip tiles strictly above the block diagonal (n0 > m0+BM-1)
__global__ __launch_bounds__(256) void gemm_nt(
    const float* __restrict__ A, const float* __restrict__ B,
    float* __restrict__ C,
    int M, int N, int K, int lda, int ldb, int ldc,
    long strideA, long strideB, long strideC,
    float alpha, int causal)
{
    int bn = blockIdx.x, bm = blockIdx.y, bz = blockIdx.z;
    int m0 = bm * BM, n0 = bn * BN;
    if (causal && n0 > m0 + (BM - 1)) return;

    A += (long)bz * strideA;
    B += (long)bz * strideB;
    C += (long)bz * strideC;

    __shared__ float As[BK][BM];
    __shared__ float Bs[BK][BN];

    int tid = threadIdx.x;
    int tx = tid & 15;        // n direction
    int ty = tid >> 4;        // m direction

    float acc[TM][TN];
#pragma unroll
    for (int i = 0; i < TM; i++)
#pragma unroll
        for (int j = 0; j < TN; j++) acc[i][j] = 0.f;

    for (int k0 = 0; k0 < K; k0 += BK) {
        // Load A tile (BM x BK) and B tile (BN x BK), both K-major, transpose to smem.
#pragma unroll
        for (int i = 0; i < 2; i++) {
            int idx = tid + i * 256;          // 0..511
            int row = idx >> 2;               // 0..127
            int c4  = idx & 3;                // 0..3  (k chunk of 4)
            float4 a = *(const float4*)&A[(size_t)(m0 + row) * lda + k0 + c4 * 4];
            As[c4 * 4 + 0][row] = a.x;
            As[c4 * 4 + 1][row] = a.y;
            As[c4 * 4 + 2][row] = a.z;
            As[c4 * 4 + 3][row] = a.w;
            float4 b = *(const float4*)&B[(size_t)(n0 + row) * ldb + k0 + c4 * 4];
            Bs[c4 * 4 + 0][row] = b.x;
            Bs[c4 * 4 + 1][row] = b.y;
            Bs[c4 * 4 + 2][row] = b.z;
            Bs[c4 * 4 + 3][row] = b.w;
        }
        __syncthreads();

#pragma unroll
        for (int k = 0; k < BK; k++) {
            float ra[TM], rb[TN];
#pragma unroll
            for (int i = 0; i < TM; i++) ra[i] = As[k][ty * TM + i];
#pragma unroll
            for (int j = 0; j < TN; j++) rb[j] = Bs[k][tx * TN + j];
#pragma unroll
            for (int i = 0; i < TM; i++)
#pragma unroll
                for (int j = 0; j < TN; j++) acc[i][j] += ra[i] * rb[j];
        }
        __syncthreads();
    }

#pragma unroll
    for (int i = 0; i < TM; i++) {
        size_t crow = (size_t)(m0 + ty * TM + i) * ldc + n0 + tx * TN;
#pragma unroll
        for (int j = 0; j < TN; j += 4) {
            float4 v;
            v.x = alpha * acc[i][j + 0];
            v.y = alpha * acc[i][j + 1];
            v.z = alpha * acc[i][j + 2];
            v.w = alpha * acc[i][j + 3];
            *(float4*)&C[crow + j] = v;
        }
    }
}

// C[m,n] = sum_k A[m,k] * B[k,n]   (A K-major, B N-major: "NN")
// causal: K-loop bounded at m0+BM (P is zero beyond the row-tile diagonal)
__global__ __launch_bounds__(256) void gemm_nn(
    const float* __restrict__ A, const float* __restrict__ B,
    float* __restrict__ C,
    int M, int N, int K, int lda, int ldb, int ldc,
    long strideA, long strideB, long strideC,
    int causal)
{
    int bn = blockIdx.x, bm = blockIdx.y, bz = blockIdx.z;
    int m0 = bm * BM, n0 = bn * BN;

    A += (long)bz * strideA;
    B += (long)bz * strideB;
    C += (long)bz * strideC;

    int Kb = causal ? min(K, m0 + BM) : K;

    __shared__ float As[BK][BM];
    __shared__ float Bs[BK][BN];

    int tid = threadIdx.x;
    int tx = tid & 15;
    int ty = tid >> 4;

    float acc[TM][TN];
#pragma unroll
    for (int i = 0; i < TM; i++)
#pragma unroll
        for (int j = 0; j < TN; j++) acc[i][j] = 0.f;

    for (int k0 = 0; k0 < Kb; k0 += BK) {
#pragma unroll
        for (int i = 0; i < 2; i++) {
            int idx = tid + i * 256;
            {   // A: BM x BK, K-major -> transpose into As
                int row = idx >> 2;
                int c4  = idx & 3;
                float4 a = *(const float4*)&A[(size_t)(m0 + row) * lda + k0 + c4 * 4];
                As[c4 * 4 + 0][row] = a.x;
                As[c4 * 4 + 1][row] = a.y;
                As[c4 * 4 + 2][row] = a.z;
                As[c4 * 4 + 3][row] = a.w;
            }
            {   // B: BK x BN, N-major -> direct copy
                int krow = idx >> 5;          // 0..15
                int c4   = idx & 31;          // 0..31
                float4 b = *(const float4*)&B[(size_t)(k0 + krow) * ldb + n0 + c4 * 4];
                *(float4*)&Bs[krow][c4 * 4] = b;
            }
        }
        __syncthreads();

#pragma unroll
        for (int k = 0; k < BK; k++) {
            float ra[TM], rb[TN];
#pragma unroll
            for (int i = 0; i < TM; i++) ra[i] = As[k][ty * TM + i];
#pragma unroll
            for (int j = 0; j < TN; j++) rb[j] = Bs[k][tx * TN + j];
#pragma unroll
            for (int i = 0; i < TM; i++)
#pragma unroll
                for (int j = 0; j < TN; j++) acc[i][j] += ra[i] * rb[j];
        }
        __syncthreads();
    }

#pragma unroll
    for (int i = 0; i < TM; i++) {
        size_t crow = (size_t)(m0 + ty * TM + i) * ldc + n0 + tx * TN;
#pragma unroll
        for (int j = 0; j < TN; j += 4) {
            float4 v;
            v.x = acc[i][j + 0];
            v.y = acc[i][j + 1];
            v.z = acc[i][j + 2];
            v.w = acc[i][j + 3];
            *(float4*)&C[crow + j] = v;
        }
    }
}

// One block per attention row (b*T + t). Softmax over [0, t], then zero-pad
// (t, tile_end) so the PV GEMM can read whole 128-wide K tiles.
__global__ __launch_bounds__(256) void softmax_causal(float* __restrict__ S, int T)
{
    int row = blockIdx.x;            // b*T + t
    int t = row & (T - 1);           // T = 4096 (pow2)
    float* p = S + (size_t)row * T;
    int len = t + 1;
    int tid = threadIdx.x;

    __shared__ float red[256];

    // 1) max
    float m = -1e30f;
    for (int i = tid; i < len; i += 256) m = fmaxf(m, p[i]);
    red[tid] = m;
    __syncthreads();
    for (int s = 128; s > 0; s >>= 1) {
        if (tid < s) red[tid] = fmaxf(red[tid], red[tid + s]);
        __syncthreads();
    }
    m = red[0];
    __syncthreads();

    // 2) exp + sum
    float sum = 0.f;
    for (int i = tid; i < len; i += 256) {
        float e = __expf(p[i] - m);
        p[i] = e;
        sum += e;
    }
    red[tid] = sum;
    __syncthreads();
    for (int s = 128; s > 0; s >>= 1) {
        if (tid < s) red[tid] += red[tid + s];
        __syncthreads();
    }
    float inv = 1.0f / red[0];

    // 3) normalize
    for (int i = tid; i < len; i += 256) p[i] *= inv;

    // 4) zero pad (t, tile_end) so PV can use full 128-wide K tiles
    int pad_end = ((t >> 7) + 1) << 7;
    for (int i = len + tid; i < pad_end; i += 256) p[i] = 0.f;
}

extern "C" void kernel_launch(void* const* d_in, const int* in_sizes, int n_in,
                              void* d_out, int out_size)
{
    const float* x     = (const float*)d_in[0];
    // d_in[1] = mask (bool tril) -- causality is hardcoded
    const float* w_qkv = (const float*)d_in[2];
    const float* w_out = (const float*)d_in[3];
    float* y = (float*)d_out;

    float *qkv, *s, *o;
    cudaGetSymbolAddress((void**)&qkv, g_qkv);
    cudaGetSymbolAddress((void**)&s,   g_s);
    cudaGetSymbolAddress((void**)&o,   g_o);

    const int M  = Bc * Tc;        // 16384
    const float scale = 0.03125f;  // C^-0.5 = 1/32

    dim3 thr(256);

    // 1) qkv = x @ w_qkv^T : [16384 x 3072], K=1024
    gemm_nt<<<dim3(3072 / BN, M / BM, 1), thr>>>(
        x, w_qkv, qkv, M, 3072, Cc, Cc, Cc, 3072,
        0, 0, 0, 1.f, 0);

    // 2) S = scale * Q K^T per batch (causal tile skip)
    //    Q = qkv + 0, K = qkv + 1024, row stride 3072
    gemm_nt<<<dim3(Tc / BN, Tc / BM, Bc), thr>>>(
        qkv, qkv + 1024, s, Tc, Tc, Cc, 3072, 3072, Tc,
        (long)Tc * 3072, (long)Tc * 3072, (long)Tc * Tc,
        scale, 1);

    // 3) row softmax + causal zero-pad
    softmax_causal<<<Bc * Tc, thr>>>(s, Tc);

    // 4) O = P V per batch (K bounded at row-tile diagonal)
    //    V = qkv + 2048, N-major with ldb=3072
    gemm_nn<<<dim3(Cc / BN, Tc / BM, Bc), thr>>>(
        s, qkv + 2048, o, Tc, Cc, Tc, Tc, 3072, Cc,
        (long)Tc * Tc, (long)Tc * 3072, (long)Tc * Cc,
        1);

    // 5) Y = O @ w_out^T : [16384 x 1024], K=1024
    gemm_nt<<<dim3(Cc / BN, M / BM, 1), thr>>>(
        o, w_out, y, M, Cc, Cc, Cc, Cc, Cc,
        0, 0, 0, 1.f, 0);
}

// round 4
// speedup vs baseline: 2.5822x; 2.5819x over previous
#include <cuda_runtime.h>
#include <cuda_bf16.h>
#include <cstdint>

// ---------------------------------------------------------------------------
// SingleHeadAttention B=4, T=4096, C=1024 — mma.sync (HMMA) split-bf16 path.
// tcgen05 is unavailable: harness PTX targets plain compute_103 (no 'a'
// features). mma.sync.m16n8k16 bf16 + ldmatrix + cp.async are sm_80+ and legal.
//   All GEMMs: C[m,n] = alpha * sum_k A[m,k]*B[n,k]  (NT, K-major operands)
//   A,B as bf16 (hi,lo) pairs; 3 MMAs per product: hh + hl + lh; fp32 acc.
// ---------------------------------------------------------------------------

static const int Bc = 4;
static const int Tc = 4096;
static const int Cc = 1024;
static const int M1 = 16384;     // B*T

#define BM 128
#define BN 128
#define BKE 64                        // bf16 k-elems per stage
#define SROW 72                       // padded smem row stride (elements)
#define MAT_BYTES (128 * SROW * 2)    // 18432 B per matrix tile
#define STAGE_BYTES (4 * MAT_BYTES)   // Ah, Al, Bh, Bl
#define SMEM_BYTES (2 * STAGE_BYTES)  // 147456 B double buffered

// ---------------- static device scratch (allocation-free rule) -------------
__device__ float g_qkv[(size_t)16384 * 3072];
__device__ float g_s  [(size_t)4 * 4096 * 4096];
__device__ float g_o  [(size_t)16384 * 1024];

__device__ __nv_bfloat16 g_xh[(size_t)16384*1024], g_xl[(size_t)16384*1024];
__device__ __nv_bfloat16 g_wqh[(size_t)3072*1024], g_wql[(size_t)3072*1024];
__device__ __nv_bfloat16 g_woh[(size_t)1024*1024], g_wol[(size_t)1024*1024];
__device__ __nv_bfloat16 g_qh[(size_t)16384*1024], g_ql[(size_t)16384*1024];
__device__ __nv_bfloat16 g_kh[(size_t)16384*1024], g_kl[(size_t)16384*1024];
__device__ __nv_bfloat16 g_vth[(size_t)4*1024*4096], g_vtl[(size_t)4*1024*4096];
__device__ __nv_bfloat16 g_ph[(size_t)4*4096*4096], g_pl[(size_t)4*4096*4096];
__device__ __nv_bfloat16 g_oh[(size_t)16384*1024], g_ol[(size_t)16384*1024];

// ---------------- helpers ---------------------------------------------------
static __device__ __forceinline__ uint32_t smem_u32(const void* p) {
    uint32_t a;
    asm("{ .reg .u64 t; cvta.to.shared.u64 t, %1; cvt.u32.u64 %0, t; }"
        : "=r"(a) : "l"(p));
    return a;
}

static __device__ __forceinline__ void cp16(uint32_t s, const void* g) {
    asm volatile("cp.async.cg.shared.global [%0], [%1], 16;"
                 :: "r"(s), "l"(g) : "memory");
}

static __device__ __forceinline__ void ldm_x4(uint32_t* r, uint32_t a) {
    asm volatile("ldmatrix.sync.aligned.m8n8.x4.shared.b16 {%0,%1,%2,%3}, [%4];"
                 : "=r"(r[0]), "=r"(r[1]), "=r"(r[2]), "=r"(r[3]) : "r"(a));
}

static __device__ __forceinline__ void ldm_x2(uint32_t* r, uint32_t a) {
    asm volatile("ldmatrix.sync.aligned.m8n8.x2.shared.b16 {%0,%1}, [%2];"
                 : "=r"(r[0]), "=r"(r[1]) : "r"(a));
}

static __device__ __forceinline__ void mma16816(float* d, const uint32_t* a,
                                                const uint32_t* b) {
    asm volatile(
        "mma.sync.aligned.m16n8k16.row.col.f32.bf16.bf16.f32 "
        "{%0,%1,%2,%3}, {%4,%5,%6,%7}, {%8,%9}, {%0,%1,%2,%3};"
        : "+f"(d[0]), "+f"(d[1]), "+f"(d[2]), "+f"(d[3])
        : "r"(a[0]), "r"(a[1]), "r"(a[2]), "r"(a[3]), "r"(b[0]), "r"(b[1]));
}

static __device__ __forceinline__ void split2(float x, __nv_bfloat16& h,
                                              __nv_bfloat16& l) {
    h = __float2bfloat16(x);
    l = __float2bfloat16(x - __bfloat162float(h));
}

// ---------------- stage loader: 16 cp.async / thread ------------------------
static __device__ __forceinline__ void load_stage(
    uint32_t st,
    const __nv_bfloat16* __restrict__ Ah, const __nv_bfloat16* __restrict__ Al,
    const __nv_bfloat16* __restrict__ Bh, const __nv_bfloat16* __restrict__ Bl,
    int m0, int n0, int k0, int lda, int ldb, int tid)
{
#pragma unroll
    for (int p = 0; p < 4; p++) {
        int idx = tid + p * 256;          // 0..1023
        int row = idx >> 3;               // 0..127
        int c   = idx & 7;                // 16B chunk in 128B of k
        uint32_t so = (uint32_t)row * (SROW * 2) + c * 16;
        size_t ga = (size_t)(m0 + row) * lda + k0 + c * 8;
        cp16(st + so,                 Ah + ga);
        cp16(st + MAT_BYTES + so,     Al + ga);
        size_t gb = (size_t)(n0 + row) * ldb + k0 + c * 8;
        cp16(st + 2 * MAT_BYTES + so, Bh + gb);
        cp16(st + 3 * MAT_BYTES + so, Bl + gb);
    }
    asm volatile("cp.async.commit_group;" ::: "memory");
}

// ---------------- HMMA split-bf16 GEMM --------------------------------------
// causal: 0 none, 1 tile-skip above diagonal (QK^T), 2 K bounded at m0+BM (PV)
__global__ void __launch_bounds__(256, 1) gemm_tc(
    const __nv_bfloat16* __restrict__ Ahi, const __nv_bfloat16* __restrict__ Alo,
    const __nv_bfloat16* __restrict__ Bhi, const __nv_bfloat16* __restrict__ Blo,
    float* __restrict__ C,
    int K, int lda, int ldb, int ldc,
    long sA, long sB, long sC,
    float alpha, int causal)
{
    int bm = blockIdx.y, bn = blockIdx.x, bz = blockIdx.z;
    int m0 = bm * BM, n0 = bn * BN;
    if (causal == 1 && n0 > m0 + BM - 1) return;

    Ahi += (size_t)bz * sA;  Alo += (size_t)bz * sA;
    Bhi += (size_t)bz * sB;  Blo += (size_t)bz * sB;
    C   += (size_t)bz * sC;

    int Kb = (causal == 2) ? ((m0 + BM < K) ? (m0 + BM) : K) : K;
    int nch = Kb / BKE;

    extern __shared__ __align__(128) char smem[];
    uint32_t sbase = smem_u32(smem);

    int tid  = threadIdx.x;
    int wid  = tid >> 5;
    int lane = tid & 31;
    int wm = wid >> 2;                 // 0..1 : warp m tile (64 rows)
    int wn = wid & 3;                  // 0..3 : warp n tile (32 cols)

    float acc[4][4][4];
#pragma unroll
    for (int i = 0; i < 4; i++)
#pragma unroll
        for (int j = 0; j < 4; j++)
#pragma unroll
            for (int r = 0; r < 4; r++) acc[i][j][r] = 0.f;

    // ldmatrix lane address components
    int l15 = lane & 15;               // A: row within 16
    int lk  = lane >> 4;               // A: k-half (0/1) * 8
    int bnr = lane & 7;                // B: n row within 8
    int bkh = (lane >> 3) & 1;         // B: k-half

    load_stage(sbase, Ahi, Alo, Bhi, Blo, m0, n0, 0, lda, ldb, tid);

    for (int c = 0; c < nch; c++) {
        if (c + 1 < nch) {
            load_stage(sbase + (uint32_t)((c + 1) & 1) * STAGE_BYTES,
                       Ahi, Alo, Bhi, Blo, m0, n0, (c + 1) * BKE, lda, ldb, tid);
            asm volatile("cp.async.wait_group 1;" ::: "memory");
        } else {
            asm volatile("cp.async.wait_group 0;" ::: "memory");
        }
        __syncthreads();

        uint32_t st  = sbase + (uint32_t)(c & 1) * STAGE_BYTES;
        uint32_t sAh = st;
        uint32_t sAl = st + MAT_BYTES;
        uint32_t sBh = st + 2 * MAT_BYTES;
        uint32_t sBl = st + 3 * MAT_BYTES;

#pragma unroll
        for (int ks = 0; ks < BKE / 16; ks++) {
            int kb = ks * 16;
            uint32_t ahi[4][4], alo[4][4], bhi[4][2], blo[4][2];
#pragma unroll
            for (int mi = 0; mi < 4; mi++) {
                uint32_t off = (uint32_t)(wm * 64 + mi * 16 + l15) * (SROW * 2)
                             + (kb + lk * 8) * 2;
                ldm_x4(ahi[mi], sAh + off);
                ldm_x4(alo[mi], sAl + off);
            }
#pragma unroll
            for (int nj = 0; nj < 4; nj++) {
                uint32_t off = (uint32_t)(wn * 32 + nj * 8 + bnr) * (SROW * 2)
                             + (kb + bkh * 8) * 2;
                ldm_x2(bhi[nj], sBh + off);
                ldm_x2(blo[nj], sBl + off);
            }
#pragma unroll
            for (int mi = 0; mi < 4; mi++)
#pragma unroll
                for (int nj = 0; nj < 4; nj++) {
                    mma16816(acc[mi][nj], ahi[mi], bhi[nj]);
                    mma16816(acc[mi][nj], ahi[mi], blo[nj]);
                    mma16816(acc[mi][nj], alo[mi], bhi[nj]);
                }
        }
        __syncthreads();
    }

    // epilogue: c0,c1 at (m=t/4, n=2(t%4)); c2,c3 at (m+8, same n)
    int gr = lane >> 2;
    int gc = (lane & 3) * 2;
#pragma unroll
    for (int mi = 0; mi < 4; mi++) {
#pragma unroll
        for (int nj = 0; nj < 4; nj++) {
            int row = m0 + wm * 64 + mi * 16 + gr;
            int col = n0 + wn * 32 + nj * 8 + gc;
            float2 v0 = make_float2(alpha * acc[mi][nj][0], alpha * acc[mi][nj][1]);
            float2 v1 = make_float2(alpha * acc[mi][nj][2], alpha * acc[mi][nj][3]);
            *(float2*)&C[(size_t)row * ldc + col] = v0;
            *(float2*)&C[(size_t)(row + 8) * ldc + col] = v1;
        }
    }
}

// ---------------- fp32 -> split bf16 (cols always 1024) ---------------------
__global__ void __launch_bounds__(256) split_f32(
    const float* __restrict__ src, __nv_bfloat16* __restrict__ hi,
    __nv_bfloat16* __restrict__ lo, size_t n, int ld)
{
    size_t i = (size_t)blockIdx.x * 256 + threadIdx.x;
    if (i >= n) return;
    size_t r = i >> 10;
    int c = (int)(i & 1023);
    float v = src[r * ld + c];
    __nv_bfloat16 h, l;
    split2(v, h, l);
    hi[i] = h;
    lo[i] = l;
}

// ---------------- V transpose + split: vt[b][c][s] = v[b][s][c] -------------
__global__ void __launch_bounds__(256) transpose_split_v(
    const float* __restrict__ qkv,
    __nv_bfloat16* __restrict__ vh, __nv_bfloat16* __restrict__ vl)
{
    __shared__ float tile[32][33];
    int b = blockIdx.z;
    int s0 = blockIdx.x * 32;
    int c0 = blockIdx.y * 32;
    const float* src = qkv + (size_t)b * 4096 * 3072 + 2048;
    int tx = threadIdx.x, ty = threadIdx.y;     // block (32, 8)
#pragma unroll
    for (int i = ty; i < 32; i += 8)
        tile[i][tx] = src[(size_t)(s0 + i) * 3072 + c0 + tx];
    __syncthreads();
    __nv_bfloat16* dh = vh + (size_t)b * 1024 * 4096;
    __nv_bfloat16* dl = vl + (size_t)b * 1024 * 4096;
#pragma unroll
    for (int i = ty; i < 32; i += 8) {
        float v = tile[tx][i];
        __nv_bfloat16 h, l;
        split2(v, h, l);
        size_t o = (size_t)(c0 + i) * 4096 + s0 + tx;
        dh[o] = h;
        dl[o] = l;
    }
}

// ---------------- causal softmax -> split bf16 P, zero-padded ---------------
__global__ void __launch_bounds__(256) softmax_split(
    float* __restrict__ S, __nv_bfloat16* __restrict__ ph,
    __nv_bfloat16* __restrict__ pl, int T)
{
    int row = blockIdx.x;                 // b*T + t
    int t = row & (T - 1);
    float* p = S + (size_t)row * T;
    __nv_bfloat16* oh = ph + (size_t)row * T;
    __nv_bfloat16* ol = pl + (size_t)row * T;
    int len = t + 1;
    int tid = threadIdx.x;

    __shared__ float red[256];

    float m = -1e30f;
    for (int i = tid; i < len; i += 256) m = fmaxf(m, p[i]);
    red[tid] = m;
    __syncthreads();
    for (int s = 128; s > 0; s >>= 1) {
        if (tid < s) red[tid] = fmaxf(red[tid], red[tid + s]);
        __syncthreads();
    }
    m = red[0];
    __syncthreads();

    float sum = 0.f;
    for (int i = tid; i < len; i += 256) {
        float e = __expf(p[i] - m);
        p[i] = e;
        sum += e;
    }
    red[tid] = sum;
    __syncthreads();
    for (int s = 128; s > 0; s >>= 1) {
        if (tid < s) red[tid] += red[tid + s];
        __syncthreads();
    }
    float inv = 1.0f / red[0];

    for (int i = tid; i < len; i += 256) {
        __nv_bfloat16 h, l;
        split2(p[i] * inv, h, l);
        oh[i] = h;
        ol[i] = l;
    }
    // zero pad to row-tile boundary (multiple of 128 >= len)
    int pad_end = ((t >> 7) + 1) << 7;
    __nv_bfloat16 z = __float2bfloat16(0.f);
    for (int i = len + tid; i < pad_end; i += 256) {
        oh[i] = z;
        ol[i] = z;
    }
}

// ---------------------------------------------------------------------------
extern "C" void kernel_launch(void* const* d_in, const int* in_sizes, int n_in,
                              void* d_out, int out_size)
{
    const float* x     = (const float*)d_in[0];
    // d_in[1] = mask (bool tril) -- causality hardcoded
    const float* w_qkv = (const float*)d_in[2];
    const float* w_out = (const float*)d_in[3];
    float* y = (float*)d_out;

    float *qkv, *s, *o;
    __nv_bfloat16 *xh, *xl, *wqh, *wql, *woh, *wol;
    __nv_bfloat16 *qh, *ql, *kh, *kl, *vth, *vtl, *ph, *pl, *oh, *ol;
    cudaGetSymbolAddress((void**)&qkv, g_qkv);
    cudaGetSymbolAddress((void**)&s,   g_s);
    cudaGetSymbolAddress((void**)&o,   g_o);
    cudaGetSymbolAddress((void**)&xh,  g_xh);  cudaGetSymbolAddress((void**)&xl,  g_xl);
    cudaGetSymbolAddress((void**)&wqh, g_wqh); cudaGetSymbolAddress((void**)&wql, g_wql);
    cudaGetSymbolAddress((void**)&woh, g_woh); cudaGetSymbolAddress((void**)&wol, g_wol);
    cudaGetSymbolAddress((void**)&qh,  g_qh);  cudaGetSymbolAddress((void**)&ql,  g_ql);
    cudaGetSymbolAddress((void**)&kh,  g_kh);  cudaGetSymbolAddress((void**)&kl,  g_kl);
    cudaGetSymbolAddress((void**)&vth, g_vth); cudaGetSymbolAddress((void**)&vtl, g_vtl);
    cudaGetSymbolAddress((void**)&ph,  g_ph);  cudaGetSymbolAddress((void**)&pl,  g_pl);
    cudaGetSymbolAddress((void**)&oh,  g_oh);  cudaGetSymbolAddress((void**)&ol,  g_ol);

    cudaFuncSetAttribute(gemm_tc, cudaFuncAttributeMaxDynamicSharedMemorySize,
                         SMEM_BYTES);

    const float scale = 0.03125f;      // C^-0.5

    // split inputs / weights
    split_f32<<<(M1*Cc + 255)/256, 256>>>(x, xh, xl, (size_t)M1*Cc, Cc);
    split_f32<<<(3072*Cc + 255)/256, 256>>>(w_qkv, wqh, wql, (size_t)3072*Cc, Cc);
    split_f32<<<(Cc*Cc + 255)/256, 256>>>(w_out, woh, wol, (size_t)Cc*Cc, Cc);

    // 1) qkv = x @ w_qkv^T   [16384 x 3072], K=1024
    gemm_tc<<<dim3(3072/BN, M1/BM, 1), 256, SMEM_BYTES>>>(
        xh, xl, wqh, wql, qkv, Cc, Cc, Cc, 3072, 0, 0, 0, 1.f, 0);

    // split Q, K; transpose+split V
    split_f32<<<(M1*Cc + 255)/256, 256>>>(qkv,        qh, ql, (size_t)M1*Cc, 3072);
    split_f32<<<(M1*Cc + 255)/256, 256>>>(qkv + 1024, kh, kl, (size_t)M1*Cc, 3072);
    transpose_split_v<<<dim3(Tc/32, Cc/32, Bc), dim3(32, 8)>>>(qkv, vth, vtl);

    // 2) S = scale * Q K^T per batch (causal tile skip)
    gemm_tc<<<dim3(Tc/BN, Tc/BM, Bc), 256, SMEM_BYTES>>>(
        qh, ql, kh, kl, s, Cc, Cc, Cc, Tc,
        (long)Tc*Cc, (long)Tc*Cc, (long)Tc*Tc, scale, 1);

    // 3) softmax -> split bf16 P (+ causal zero-pad)
    softmax_split<<<Bc*Tc, 256>>>(s, ph, pl, Tc);

    // 4) O = P V per batch: C[t,c] = sum_s P[t,s] * Vt[c,s]  (K bounded)
    gemm_tc<<<dim3(Cc/BN, Tc/BM, Bc), 256, SMEM_BYTES>>>(
        ph, pl, vth, vtl, o, Tc, Tc, Tc, Cc,
        (long)Tc*Tc, (long)Cc*Tc, (long)Tc*Cc, 1.f, 2);

    // split O
    split_f32<<<(M1*Cc + 255)/256, 256>>>(o, oh, ol, (size_t)M1*Cc, Cc);

    // 5) Y = O @ w_out^T   [16384 x 1024], K=1024
    gemm_tc<<<dim3(Cc/BN, M1/BM, 1), 256, SMEM_BYTES>>>(
        oh, ol, woh, wol, y, Cc, Cc, Cc, Cc, 0, 0, 0, 1.f, 0);
}

// round 5
// speedup vs baseline: 2.7484x; 1.0644x over previous
#include <cuda_runtime.h>
#include <cuda_bf16.h>
#include <cstdint>

// ---------------------------------------------------------------------------
// SingleHeadAttention B=4, T=4096, C=1024 — mma.sync split-bf16, round 5.
//   3-stage cp.async pipeline, ldm_x4 for B, fused split epilogues.
//   All GEMMs: C[m,n] = alpha * sum_k A[m,k]*B[n,k]  (NT, K-major operands)
//   A,B as bf16 (hi,lo); 3 MMAs per product: hh + hl + lh; fp32 acc.
// ---------------------------------------------------------------------------

static const int Bc = 4;
static const int Tc = 4096;
static const int Cc = 1024;
static const int M1 = 16384;     // B*T

#define BM 128
#define BN 128
#define BKE 64                        // bf16 k-elems per stage
#define SROW 72                       // padded smem row stride (elements)
#define MAT_BYTES (128 * SROW * 2)    // 18432 B per matrix tile
#define STAGE_BYTES (4 * MAT_BYTES)   // Ah, Al, Bh, Bl = 73728
#define NSTAGE 3
#define SMEM_BYTES (NSTAGE * STAGE_BYTES)  // 221184 B

// ---------------- static device scratch (allocation-free rule) -------------
__device__ float g_s  [(size_t)4 * 4096 * 4096];
__device__ float g_v  [(size_t)16384 * 1024];

__device__ __nv_bfloat16 g_xh[(size_t)16384*1024], g_xl[(size_t)16384*1024];
__device__ __nv_bfloat16 g_wqh[(size_t)3072*1024], g_wql[(size_t)3072*1024];
__device__ __nv_bfloat16 g_woh[(size_t)1024*1024], g_wol[(size_t)1024*1024];
__device__ __nv_bfloat16 g_qh[(size_t)16384*1024], g_ql[(size_t)16384*1024];
__device__ __nv_bfloat16 g_kh[(size_t)16384*1024], g_kl[(size_t)16384*1024];
__device__ __nv_bfloat16 g_vth[(size_t)4*1024*4096], g_vtl[(size_t)4*1024*4096];
__device__ __nv_bfloat16 g_ph[(size_t)4*4096*4096], g_pl[(size_t)4*4096*4096];
__device__ __nv_bfloat16 g_oh[(size_t)16384*1024], g_ol[(size_t)16384*1024];

// ---------------- helpers ---------------------------------------------------
static __device__ __forceinline__ uint32_t smem_u32(const void* p) {
    uint32_t a;
    asm("{ .reg .u64 t; cvta.to.shared.u64 t, %1; cvt.u32.u64 %0, t; }"
        : "=r"(a) : "l"(p));
    return a;
}

static __device__ __forceinline__ void cp16(uint32_t s, const void* g) {
    asm volatile("cp.async.cg.shared.global [%0], [%1], 16;"
                 :: "r"(s), "l"(g) : "memory");
}

static __device__ __forceinline__ void ldm_x4(uint32_t* r, uint32_t a) {
    asm volatile("ldmatrix.sync.aligned.m8n8.x4.shared.b16 {%0,%1,%2,%3}, [%4];"
                 : "=r"(r[0]), "=r"(r[1]), "=r"(r[2]), "=r"(r[3]) : "r"(a));
}

static __device__ __forceinline__ void mma16816(float* d, const uint32_t* a,
                                                const uint32_t* b) {
    asm volatile(
        "mma.sync.aligned.m16n8k16.row.col.f32.bf16.bf16.f32 "
        "{%0,%1,%2,%3}, {%4,%5,%6,%7}, {%8,%9}, {%0,%1,%2,%3};"
        : "+f"(d[0]), "+f"(d[1]), "+f"(d[2]), "+f"(d[3])
        : "r"(a[0]), "r"(a[1]), "r"(a[2]), "r"(a[3]), "r"(b[0]), "r"(b[1]));
}

static __device__ __forceinline__ void split2(float x, __nv_bfloat16& h,
                                              __nv_bfloat16& l) {
    h = __float2bfloat16(x);
    l = __float2bfloat16(x - __bfloat162float(h));
}

// ---------------- stage loader: 16 cp.async / thread ------------------------
static __device__ __forceinline__ void load_stage(
    uint32_t st,
    const __nv_bfloat16* __restrict__ Ah, const __nv_bfloat16* __restrict__ Al,
    const __nv_bfloat16* __restrict__ Bh, const __nv_bfloat16* __restrict__ Bl,
    int m0, int n0, int k0, int lda, int ldb, int tid)
{
#pragma unroll
    for (int p = 0; p < 4; p++) {
        int idx = tid + p * 256;          // 0..1023
        int row = idx >> 3;               // 0..127
        int c   = idx & 7;                // 16B chunk in 128B of k
        uint32_t so = (uint32_t)row * (SROW * 2) + c * 16;
        size_t ga = (size_t)(m0 + row) * lda + k0 + c * 8;
        cp16(st + so,                 Ah + ga);
        cp16(st + MAT_BYTES + so,     Al + ga);
        size_t gb = (size_t)(n0 + row) * ldb + k0 + c * 8;
        cp16(st + 2 * MAT_BYTES + so, Bh + gb);
        cp16(st + 3 * MAT_BYTES + so, Bl + gb);
    }
    asm volatile("cp.async.commit_group;" ::: "memory");
}

// ---------------- HMMA split-bf16 GEMM --------------------------------------
// causal: 0 none, 1 tile-skip above diagonal (QK^T), 2 K bounded at m0+BM (PV)
// mode: 0 = fp32 C -> o0 ; 1 = split bf16 -> o0(hi), o1(lo) ; 2 = QKV scatter
__global__ void __launch_bounds__(256, 1) gemm_tc(
    const __nv_bfloat16* __restrict__ Ahi, const __nv_bfloat16* __restrict__ Alo,
    const __nv_bfloat16* __restrict__ Bhi, const __nv_bfloat16* __restrict__ Blo,
    void* o0, void* o1,
    int K, int lda, int ldb, int ldc,
    long sA, long sB, long sC,
    float alpha, int causal, int mode)
{
    int bm = blockIdx.y, bn = blockIdx.x, bz = blockIdx.z;
    int m0 = bm * BM, n0 = bn * BN;
    if (causal == 1 && n0 > m0 + BM - 1) return;

    Ahi += (size_t)bz * sA;  Alo += (size_t)bz * sA;
    Bhi += (size_t)bz * sB;  Blo += (size_t)bz * sB;

    int Kb = (causal == 2) ? ((m0 + BM < K) ? (m0 + BM) : K) : K;
    int nch = Kb / BKE;                  // >= 2 always here

    extern __shared__ __align__(128) char smem[];
    uint32_t sbase = smem_u32(smem);

    int tid  = threadIdx.x;
    int wid  = tid >> 5;
    int lane = tid & 31;
    int wm = wid >> 2;                 // 0..1 : warp m tile (64 rows)
    int wn = wid & 3;                  // 0..3 : warp n tile (32 cols)

    float acc[4][4][4];
#pragma unroll
    for (int i = 0; i < 4; i++)
#pragma unroll
        for (int j = 0; j < 4; j++)
#pragma unroll
            for (int r = 0; r < 4; r++) acc[i][j][r] = 0.f;

    // ldmatrix lane address components
    int l15 = lane & 15;               // A: row within 16
    int lk  = lane >> 4;               // A: k-half (0/1)
    int brow = ((lane >> 4) & 1) * 8 + (lane & 7);   // B x4: row within 16
    int bkh  = (lane >> 3) & 1;                      // B: k-half

    load_stage(sbase, Ahi, Alo, Bhi, Blo, m0, n0, 0, lda, ldb, tid);
    load_stage(sbase + STAGE_BYTES, Ahi, Alo, Bhi, Blo, m0, n0, BKE, lda, ldb, tid);

    for (int c = 0; c < nch; c++) {
        if (c + 1 < nch)
            asm volatile("cp.async.wait_group 1;" ::: "memory");
        else
            asm volatile("cp.async.wait_group 0;" ::: "memory");
        __syncthreads();

        if (c + 2 < nch)
            load_stage(sbase + (uint32_t)((c + 2) % NSTAGE) * STAGE_BYTES,
                       Ahi, Alo, Bhi, Blo, m0, n0, (c + 2) * BKE, lda, ldb, tid);

        uint32_t st  = sbase + (uint32_t)(c % NSTAGE) * STAGE_BYTES;
        uint32_t sAh = st;
        uint32_t sAl = st + MAT_BYTES;
        uint32_t sBh = st + 2 * MAT_BYTES;
        uint32_t sBl = st + 3 * MAT_BYTES;

#pragma unroll
        for (int ks = 0; ks < BKE / 16; ks++) {
            int kb = ks * 16;
            uint32_t ahi[4][4], alo[4][4], bhi[2][4], blo[2][4];
#pragma unroll
            for (int mi = 0; mi < 4; mi++) {
                uint32_t off = (uint32_t)(wm * 64 + mi * 16 + l15) * (SROW * 2)
                             + (kb + lk * 8) * 2;
                ldm_x4(ahi[mi], sAh + off);
                ldm_x4(alo[mi], sAl + off);
            }
#pragma unroll
            for (int np = 0; np < 2; np++) {
                uint32_t off = (uint32_t)(wn * 32 + np * 16 + brow) * (SROW * 2)
                             + (kb + bkh * 8) * 2;
                ldm_x4(bhi[np], sBh + off);
                ldm_x4(blo[np], sBl + off);
            }
#pragma unroll
            for (int mi = 0; mi < 4; mi++)
#pragma unroll
                for (int nj = 0; nj < 4; nj++) {
                    const uint32_t* bh = &bhi[nj >> 1][(nj & 1) * 2];
                    const uint32_t* bl = &blo[nj >> 1][(nj & 1) * 2];
                    mma16816(acc[mi][nj], ahi[mi], bh);
                    mma16816(acc[mi][nj], ahi[mi], bl);
                    mma16816(acc[mi][nj], alo[mi], bh);
                }
        }
    }

    // ---------------- epilogue ----------------
    int gr = lane >> 2;
    int gc = (lane & 3) * 2;

    if (mode == 0) {
        float* C = (float*)o0 + (size_t)bz * sC;
#pragma unroll
        for (int mi = 0; mi < 4; mi++)
#pragma unroll
            for (int nj = 0; nj < 4; nj++) {
                int row = m0 + wm * 64 + mi * 16 + gr;
                int col = n0 + wn * 32 + nj * 8 + gc;
                float2 v0 = make_float2(alpha * acc[mi][nj][0], alpha * acc[mi][nj][1]);
                float2 v1 = make_float2(alpha * acc[mi][nj][2], alpha * acc[mi][nj][3]);
                *(float2*)((float*)C + (size_t)row * ldc + col) = v0;
                *(float2*)((float*)C + (size_t)(row + 8) * ldc + col) = v1;
            }
    } else if (mode == 1) {
        __nv_bfloat16* Oh = (__nv_bfloat16*)o0 + (size_t)bz * sC;
        __nv_bfloat16* Ol = (__nv_bfloat16*)o1 + (size_t)bz * sC;
#pragma unroll
        for (int mi = 0; mi < 4; mi++)
#pragma unroll
            for (int nj = 0; nj < 4; nj++) {
                int row = m0 + wm * 64 + mi * 16 + gr;
                int col = n0 + wn * 32 + nj * 8 + gc;
#pragma unroll
                for (int h = 0; h < 2; h++) {
                    __nv_bfloat16 h0, l0, h1, l1;
                    split2(acc[mi][nj][h * 2 + 0], h0, l0);
                    split2(acc[mi][nj][h * 2 + 1], h1, l1);
                    size_t off = (size_t)(row + h * 8) * ldc + col;
                    *(__nv_bfloat162*)(Oh + off) = __nv_bfloat162(h0, h1);
                    *(__nv_bfloat162*)(Ol + off) = __nv_bfloat162(l0, l1);
                }
            }
    } else {
        // mode 2: QKV scatter. region by n0: [0,1024) Q, [1024,2048) K, else V.
        int region = n0 >> 10;
        int cb = n0 & 1023;
        __nv_bfloat16* Dh = (region == 0) ? g_qh : g_kh;
        __nv_bfloat16* Dl = (region == 0) ? g_ql : g_kl;
#pragma unroll
        for (int mi = 0; mi < 4; mi++)
#pragma unroll
            for (int nj = 0; nj < 4; nj++) {
                int row = m0 + wm * 64 + mi * 16 + gr;
                int col = cb + wn * 32 + nj * 8 + gc;
#pragma unroll
                for (int h = 0; h < 2; h++) {
                    size_t off = (size_t)(row + h * 8) * 1024 + col;
                    if (region == 2) {
                        *(float2*)(g_v + off) =
                            make_float2(acc[mi][nj][h * 2 + 0], acc[mi][nj][h * 2 + 1]);
                    } else {
                        __nv_bfloat16 h0, l0, h1, l1;
                        split2(acc[mi][nj][h * 2 + 0], h0, l0);
                        split2(acc[mi][nj][h * 2 + 1], h1, l1);
                        *(__nv_bfloat162*)(Dh + off) = __nv_bfloat162(h0, h1);
                        *(__nv_bfloat162*)(Dl + off) = __nv_bfloat162(l0, l1);
                    }
                }
            }
    }
}

// ---------------- fp32 -> split bf16 (inputs) --------------------------------
__global__ void __launch_bounds__(256) split_f32(
    const float* __restrict__ src, __nv_bfloat16* __restrict__ hi,
    __nv_bfloat16* __restrict__ lo, size_t n)
{
    size_t i = (size_t)blockIdx.x * 256 + threadIdx.x;
    if (i >= n) return;
    float v = src[i];
    __nv_bfloat16 h, l;
    split2(v, h, l);
    hi[i] = h;
    lo[i] = l;
}

// ---------------- V transpose + split: vt[b][c][s] = v[b][s][c] -------------
__global__ void __launch_bounds__(256) transpose_split_v(
    const float* __restrict__ v,
    __nv_bfloat16* __restrict__ vh, __nv_bfloat16* __restrict__ vl)
{
    __shared__ float tile[32][33];
    int b = blockIdx.z;
    int s0 = blockIdx.x * 32;
    int c0 = blockIdx.y * 32;
    const float* src = v + (size_t)b * 4096 * 1024;
    int tx = threadIdx.x, ty = threadIdx.y;     // block (32, 8)
#pragma unroll
    for (int i = ty; i < 32; i += 8)
        tile[i][tx] = src[(size_t)(s0 + i) * 1024 + c0 + tx];
    __syncthreads();
    __nv_bfloat16* dh = vh + (size_t)b * 1024 * 4096;
    __nv_bfloat16* dl = vl + (size_t)b * 1024 * 4096;
#pragma unroll
    for (int i = ty; i < 32; i += 8) {
        float val = tile[tx][i];
        __nv_bfloat16 h, l;
        split2(val, h, l);
        size_t o = (size_t)(c0 + i) * 4096 + s0 + tx;
        dh[o] = h;
        dl[o] = l;
    }
}

// ---------------- causal softmax -> split bf16 P, zero-padded ---------------
__global__ void __launch_bounds__(256) softmax_split(
    float* __restrict__ S, __nv_bfloat16* __restrict__ ph,
    __nv_bfloat16* __restrict__ pl, int T)
{
    int row = blockIdx.x;                 // b*T + t
    int t = row & (T - 1);
    float* p = S + (size_t)row * T;
    __nv_bfloat16* oh = ph + (size_t)row * T;
    __nv_bfloat16* ol = pl + (size_t)row * T;
    int len = t + 1;
    int tid = threadIdx.x;

    __shared__ float red[256];

    float m = -1e30f;
    for (int i = tid; i < len; i += 256) m = fmaxf(m, p[i]);
    red[tid] = m;
    __syncthreads();
    for (int s = 128; s > 0; s >>= 1) {
        if (tid < s) red[tid] = fmaxf(red[tid], red[tid + s]);
        __syncthreads();
    }
    m = red[0];
    __syncthreads();

    float sum = 0.f;
    for (int i = tid; i < len; i += 256) {
        float e = __expf(p[i] - m);
        p[i] = e;
        sum += e;
    }
    red[tid] = sum;
    __syncthreads();
    for (int s = 128; s > 0; s >>= 1) {
        if (tid < s) red[tid] += red[tid + s];
        __syncthreads();
    }
    float inv = 1.0f / red[0];

    for (int i = tid; i < len; i += 256) {
        __nv_bfloat16 h, l;
        split2(p[i] * inv, h, l);
        oh[i] = h;
        ol[i] = l;
    }
    // zero pad to row-tile boundary (multiple of 128 >= len)
    int pad_end = ((t >> 7) + 1) << 7;
    __nv_bfloat16 z = __float2bfloat16(0.f);
    for (int i = len + tid; i < pad_end; i += 256) {
        oh[i] = z;
        ol[i] = z;
    }
}

// ---------------------------------------------------------------------------
extern "C" void kernel_launch(void* const* d_in, const int* in_sizes, int n_in,
                              void* d_out, int out_size)
{
    const float* x     = (const float*)d_in[0];
    // d_in[1] = mask (bool tril) -- causality hardcoded
    const float* w_qkv = (const float*)d_in[2];
    const float* w_out = (const float*)d_in[3];
    float* y = (float*)d_out;

    float *s, *v;
    __nv_bfloat16 *xh, *xl, *wqh, *wql, *woh, *wol;
    __nv_bfloat16 *qh, *ql, *kh, *kl, *vth, *vtl, *ph, *pl, *oh, *ol;
    cudaGetSymbolAddress((void**)&s,   g_s);
    cudaGetSymbolAddress((void**)&v,   g_v);
    cudaGetSymbolAddress((void**)&xh,  g_xh);  cudaGetSymbolAddress((void**)&xl,  g_xl);
    cudaGetSymbolAddress((void**)&wqh, g_wqh); cudaGetSymbolAddress((void**)&wql, g_wql);
    cudaGetSymbolAddress((void**)&woh, g_woh); cudaGetSymbolAddress((void**)&wol, g_wol);
    cudaGetSymbolAddress((void**)&qh,  g_qh);  cudaGetSymbolAddress((void**)&ql,  g_ql);
    cudaGetSymbolAddress((void**)&kh,  g_kh);  cudaGetSymbolAddress((void**)&kl,  g_kl);
    cudaGetSymbolAddress((void**)&vth, g_vth); cudaGetSymbolAddress((void**)&vtl, g_vtl);
    cudaGetSymbolAddress((void**)&ph,  g_ph);  cudaGetSymbolAddress((void**)&pl,  g_pl);
    cudaGetSymbolAddress((void**)&oh,  g_oh);  cudaGetSymbolAddress((void**)&ol,  g_ol);

    cudaFuncSetAttribute(gemm_tc, cudaFuncAttributeMaxDynamicSharedMemorySize,
                         SMEM_BYTES);

    const float scale = 0.03125f;      // C^-0.5

    // split inputs / weights
    split_f32<<<(M1*Cc + 255)/256, 256>>>(x, xh, xl, (size_t)M1*Cc);
    split_f32<<<(3072*Cc + 255)/256, 256>>>(w_qkv, wqh, wql, (size_t)3072*Cc);
    split_f32<<<(Cc*Cc + 255)/256, 256>>>(w_out, woh, wol, (size_t)Cc*Cc);

    // 1) qkv = x @ w_qkv^T, fused scatter: Q,K -> split bf16, V -> fp32
    gemm_tc<<<dim3(3072/BN, M1/BM, 1), 256, SMEM_BYTES>>>(
        xh, xl, wqh, wql, nullptr, nullptr,
        Cc, Cc, Cc, 0, 0, 0, 0, 1.f, 0, 2);

    // transpose + split V
    transpose_split_v<<<dim3(Tc/32, Cc/32, Bc), dim3(32, 8)>>>(v, vth, vtl);

    // 2) S = scale * Q K^T per batch (causal tile skip)
    gemm_tc<<<dim3(Tc/BN, Tc/BM, Bc), 256, SMEM_BYTES>>>(
        qh, ql, kh, kl, s, nullptr,
        Cc, Cc, Cc, Tc, (long)Tc*Cc, (long)Tc*Cc, (long)Tc*Tc,
        scale, 1, 0);

    // 3) softmax -> split bf16 P (+ causal zero-pad)
    softmax_split<<<Bc*Tc, 256>>>(s, ph, pl, Tc);

    // 4) O = P V per batch (K bounded), fused split epilogue -> oh/ol
    gemm_tc<<<dim3(Cc/BN, Tc/BM, Bc), 256, SMEM_BYTES>>>(
        ph, pl, vth, vtl, oh, ol,
        Tc, Tc, Tc, Cc, (long)Tc*Tc, (long)Cc*Tc, (long)Tc*Cc,
        1.f, 2, 1);

    // 5) Y = O @ w_out^T
    gemm_tc<<<dim3(Cc/BN, M1/BM, 1), 256, SMEM_BYTES>>>(
        oh, ol, woh, wol, y, nullptr,
        Cc, Cc, Cc, Cc, 0, 0, 0, 1.f, 0, 0);
}